// round 14
// baseline (speedup 1.0000x reference)
#include <cuda_runtime.h>
#include <cuda_bf16.h>
#include <math.h>
#include <stdint.h>

#define EPS  1e-5f
#define HHH  192
// smem layout (u32/float offsets)
#define CPO  0                 // params: up to 6 x 64 floats (384)
#define XHO  384               // X hi: 128 rows x 36 u32 (bf16x2 per k-pair)
#define XLO  4992              // X lo: 128 x 36
#define WHO  9600              // W hi: 16 pair-rows x 68 float2 (2176 u32)
#define WLO  11776             // W lo: same
#define SMF  13952
#define SMB  (SMF * 4)         // 55808 bytes

// Scratch (device globals — allocation-free)
__device__ __align__(16) float g_S[32 * 64 * 64 * 64];        // 3x3 sub-block sums; reused as unique-row output
__device__ __align__(16) float g_tok[2 * 32 * 32 * 32 * 64];  // tokens [p][b][i][j][c]

__device__ __forceinline__ unsigned short f2b(float x) {
    return __bfloat16_as_ushort(__float2bfloat16_rn(x));
}
__device__ __forceinline__ float b2f(unsigned short u) {
    return __uint_as_float(((uint32_t)u) << 16);
}
__device__ __forceinline__ void mma16(float* d, const uint32_t* a, uint32_t b0, uint32_t b1) {
    asm volatile(
        "mma.sync.aligned.m16n8k16.row.col.f32.bf16.bf16.f32 "
        "{%0,%1,%2,%3}, {%4,%5,%6,%7}, {%8,%9}, {%0,%1,%2,%3};"
        : "+f"(d[0]), "+f"(d[1]), "+f"(d[2]), "+f"(d[3])
        : "r"(a[0]), "r"(a[1]), "r"(a[2]), "r"(a[3]), "r"(b0), "r"(b1));
}
__device__ __forceinline__ float gelu_exact(float v) {
    return 0.5f * v * (1.0f + erff(v * 0.7071067811865476f));
}

// ---------------------------------------------------------------------------
// K1: 3x3 sub-block sums (85% of DRAM roofline — unchanged).
// ---------------------------------------------------------------------------
__global__ void __launch_bounds__(256) k1_subsum(const float* __restrict__ x) {
    int tid = blockIdx.x * blockDim.x + threadIdx.x;
    int c4 = tid & 15;
    int sw = (tid >> 4) & 63;
    int sh = (tid >> 10) & 63;
    int b  = tid >> 16;
    const float4* x4 = (const float4*)x;
    float4 acc = make_float4(0.f, 0.f, 0.f, 0.f);
    int rowbase = (b * HHH + sh * 3) * HHH + sw * 3;
#pragma unroll
    for (int dh = 0; dh < 3; dh++)
#pragma unroll
        for (int dw = 0; dw < 3; dw++) {
            float4 v = x4[(rowbase + dh * HHH + dw) * 16 + c4];
            acc.x += v.x; acc.y += v.y; acc.z += v.z; acc.w += v.w;
        }
    ((float4*)g_S)[tid] = acc;
}

// split 4 consecutive k (k=4c4..4c4+3) of row r into packed bf16x2 hi/lo tiles
__device__ __forceinline__ void store_x4(float* sm, int r, int c4, float4 xv) {
    unsigned short h0 = f2b(xv.x), h1 = f2b(xv.y), h2 = f2b(xv.z), h3 = f2b(xv.w);
    uint32_t hh0 = (uint32_t)h0 | ((uint32_t)h1 << 16);
    uint32_t hh1 = (uint32_t)h2 | ((uint32_t)h3 << 16);
    unsigned short l0 = f2b(xv.x - b2f(h0)), l1 = f2b(xv.y - b2f(h1));
    unsigned short l2 = f2b(xv.z - b2f(h2)), l3 = f2b(xv.w - b2f(h3));
    uint32_t ll0 = (uint32_t)l0 | ((uint32_t)l1 << 16);
    uint32_t ll1 = (uint32_t)l2 | ((uint32_t)l3 << 16);
    ((uint2*)(sm + XHO))[r * 18 + c4] = make_uint2(hh0, hh1);
    ((uint2*)(sm + XLO))[r * 18 + c4] = make_uint2(ll0, ll1);
}

// W[k][n] (64x64) -> paired bf16x2 hi/lo tiles.
__device__ __forceinline__ void load_wsplit(const float* __restrict__ W, float* sm, int tid) {
    unsigned short* wh16 = (unsigned short*)(sm + WHO);
    unsigned short* wl16 = (unsigned short*)(sm + WLO);
#pragma unroll
    for (int e = 0; e < 4; e++) {
        int idx = e * 256 + tid;
        int k = idx >> 4, n4 = idx & 15;
        float4 wv = ((const float4*)W)[idx];
        int ks = k >> 4, kk = k & 15, pkl = kk >> 1;
        int row = ks * 4 + (pkl & 3), half = pkl >> 2, par = kk & 1;
        float vv[4] = { wv.x, wv.y, wv.z, wv.w };
#pragma unroll
        for (int jj = 0; jj < 4; jj++) {
            int n = 4 * n4 + jj;
            int u16i = ((((row * 68 + n) * 2 + half) << 1) | par);
            unsigned short hb = f2b(vv[jj]);
            wh16[u16i] = hb;
            wl16[u16i] = f2b(vv[jj] - b2f(hb));
        }
    }
}

// GEMM(128x64 @ 64x64) via mma.sync bf16 m16n8k16, 3-pass split + LN + GELU.
__device__ __forceinline__ void gemm_ln_gelu(const float* sm, const float* cp, int tid,
                                             float v[2][16]) {
    int w = tid >> 5, lane = tid & 31, g = lane >> 2, q = lane & 3;
    const uint32_t* xh = (const uint32_t*)(sm + XHO);
    const uint32_t* xl = (const uint32_t*)(sm + XLO);
    const uint2* wh2 = (const uint2*)(sm + WHO);
    const uint2* wl2 = (const uint2*)(sm + WLO);
    float acc[8][4];
#pragma unroll
    for (int j = 0; j < 8; j++) {
        float2 b2 = *(const float2*)(cp + 8 * j + 2 * q);
        acc[j][0] = b2.x; acc[j][1] = b2.y; acc[j][2] = b2.x; acc[j][3] = b2.y;
    }
    int r0 = 16 * w;
    const uint32_t* xh0 = xh + (r0 + g) * 36;
    const uint32_t* xh1 = xh + (r0 + 8 + g) * 36;
    const uint32_t* xl0 = xl + (r0 + g) * 36;
    const uint32_t* xl1 = xl + (r0 + 8 + g) * 36;
#pragma unroll
    for (int ks = 0; ks < 4; ks++) {
        int pk = 8 * ks + q;
        uint32_t Ahi[4] = { xh0[pk], xh1[pk], xh0[pk + 4], xh1[pk + 4] };
        uint32_t Alo[4] = { xl0[pk], xl1[pk], xl0[pk + 4], xl1[pk + 4] };
        const uint2* whr = wh2 + (ks * 4 + q) * 68 + g;
        const uint2* wlr = wl2 + (ks * 4 + q) * 68 + g;
#pragma unroll
        for (int jh = 0; jh < 2; jh++) {
            uint2 wh[4], wl[4];
#pragma unroll
            for (int j4 = 0; j4 < 4; j4++) {
                wh[j4] = whr[8 * (4 * jh + j4)];
                wl[j4] = wlr[8 * (4 * jh + j4)];
            }
#pragma unroll
            for (int j4 = 0; j4 < 4; j4++) mma16(acc[4*jh+j4], Ahi, wh[j4].x, wh[j4].y);
#pragma unroll
            for (int j4 = 0; j4 < 4; j4++) mma16(acc[4*jh+j4], Ahi, wl[j4].x, wl[j4].y);
#pragma unroll
            for (int j4 = 0; j4 < 4; j4++) mma16(acc[4*jh+j4], Alo, wh[j4].x, wh[j4].y);
        }
    }
#pragma unroll
    for (int j = 0; j < 8; j++) {
        v[0][2 * j] = acc[j][0]; v[0][2 * j + 1] = acc[j][1];
        v[1][2 * j] = acc[j][2]; v[1][2 * j + 1] = acc[j][3];
    }
#pragma unroll
    for (int t = 0; t < 2; t++) {
        float s = 0.f;
#pragma unroll
        for (int i = 0; i < 16; i++) s += v[t][i];
        s += __shfl_xor_sync(0xffffffffu, s, 1);
        s += __shfl_xor_sync(0xffffffffu, s, 2);
        float mean = s * (1.0f / 64.0f);
        float var = 0.f;
#pragma unroll
        for (int i = 0; i < 16; i++) { float d = v[t][i] - mean; var += d * d; }
        var += __shfl_xor_sync(0xffffffffu, var, 1);
        var += __shfl_xor_sync(0xffffffffu, var, 2);
        float rstd = rsqrtf(var * (1.0f / 64.0f) + EPS);
#pragma unroll
        for (int j = 0; j < 8; j++) {
            float2 gm = *(const float2*)(cp + 64  + 8 * j + 2 * q);
            float2 bt = *(const float2*)(cp + 128 + 8 * j + 2 * q);
            v[t][2 * j]     = gelu_exact((v[t][2 * j]     - mean) * rstd * gm.x + bt.x);
            v[t][2 * j + 1] = gelu_exact((v[t][2 * j + 1] - mean) * rstd * gm.y + bt.y);
        }
    }
}

// write layer activations back as split bf16x2 (cols 8j+2q form a k-pair)
__device__ __forceinline__ void writeback_split(float* sm, int tid, const float v[2][16]) {
    uint32_t* xh = (uint32_t*)(sm + XHO);
    uint32_t* xl = (uint32_t*)(sm + XLO);
    int w = tid >> 5, lane = tid & 31, g = lane >> 2, q = lane & 3;
#pragma unroll
    for (int t = 0; t < 2; t++) {
        int r = 16 * w + g + 8 * t;
#pragma unroll
        for (int j = 0; j < 8; j++) {
            int pk = 4 * j + q;
            float a = v[t][2 * j], b = v[t][2 * j + 1];
            unsigned short ha = f2b(a), hb = f2b(b);
            xh[r * 36 + pk] = (uint32_t)ha | ((uint32_t)hb << 16);
            unsigned short la = f2b(a - b2f(ha)), lb = f2b(b - b2f(hb));
            xl[r * 36 + pk] = (uint32_t)la | ((uint32_t)lb << 16);
        }
    }
}

// ---------------------------------------------------------------------------
// K2: token projection (both paths). 128 rows/CTA, 512 CTAs.
// ---------------------------------------------------------------------------
__global__ void __launch_bounds__(256, 3) k2_token(
    const float* __restrict__ tW, const float* __restrict__ tb,
    const float* __restrict__ tg, const float* __restrict__ tbe)
{
    extern __shared__ __align__(16) float sm[];
    int tid = threadIdx.x;
    if (tid < 64) {
        sm[CPO + tid] = tb[tid]; sm[CPO + 64 + tid] = tg[tid]; sm[CPO + 128 + tid] = tbe[tid];
    }
    load_wsplit(tW, sm, tid);
    int R0 = blockIdx.x * 128;
#pragma unroll 2
    for (int e = 0; e < 8; e++) {
        int idx = e * 256 + tid;
        int r = idx >> 4, c4 = idx & 15;
        int R = R0 + r;
        int p = R >> 15, rem = R & 32767;
        int bb = rem >> 10, ii = (rem >> 5) & 31, jj = rem & 31;
        int r0, r1, q0, q1;
        if (p == 0) { r0 = 2 * ii;            r1 = 2 * ii + 1;
                      q0 = 2 * jj;            q1 = 2 * jj + 1; }
        else        { r0 = (2 * ii + 1) & 63; r1 = (2 * ii + 2) & 63;
                      q0 = (2 * jj + 1) & 63; q1 = (2 * jj + 2) & 63; }
        const float4* Sb = (const float4*)g_S + bb * 65536;
        float4 s0 = Sb[(r0 * 64 + q0) * 16 + c4];
        float4 s1 = Sb[(r0 * 64 + q1) * 16 + c4];
        float4 s2 = Sb[(r1 * 64 + q0) * 16 + c4];
        float4 s3 = Sb[(r1 * 64 + q1) * 16 + c4];
        store_x4(sm, r, c4,
            make_float4((s0.x + s1.x + s2.x + s3.x) * (1.0f / 36.0f),
                        (s0.y + s1.y + s2.y + s3.y) * (1.0f / 36.0f),
                        (s0.z + s1.z + s2.z + s3.z) * (1.0f / 36.0f),
                        (s0.w + s1.w + s2.w + s3.w) * (1.0f / 36.0f)));
    }
    __syncthreads();
    float v[2][16];
    gemm_ln_gelu(sm, sm + CPO, tid, v);
    int w = tid >> 5, lane = tid & 31, g = lane >> 2, q = lane & 3;
    int R = R0 + 16 * w + g;
#pragma unroll
    for (int j = 0; j < 8; j++) {
        *(float2*)&g_tok[R * 64 + 8 * j + 2 * q]       = make_float2(v[0][2*j], v[0][2*j+1]);
        *(float2*)&g_tok[(R + 8) * 64 + 8 * j + 2 * q] = make_float2(v[1][2*j], v[1][2*j+1]);
    }
}

// ---------------------------------------------------------------------------
// K3a: fuse + out layers per unique 3x3 block (128 rows/CTA, 1024 CTAs);
// write unique rows into g_S (dead after K2). No broadcast here.
// ---------------------------------------------------------------------------
__global__ void __launch_bounds__(256, 3) k3a_compute(
    const float* __restrict__ fW, const float* __restrict__ fb,
    const float* __restrict__ fg, const float* __restrict__ fbe,
    const float* __restrict__ oW, const float* __restrict__ ob,
    const float* __restrict__ og, const float* __restrict__ obe)
{
    extern __shared__ __align__(16) float sm[];
    int tid = threadIdx.x;
    if (tid < 64) {
        sm[CPO + tid]       = fb[tid]; sm[CPO + 64 + tid]  = fg[tid]; sm[CPO + 128 + tid] = fbe[tid];
        sm[CPO + 192 + tid] = ob[tid]; sm[CPO + 256 + tid] = og[tid]; sm[CPO + 320 + tid] = obe[tid];
    }
    load_wsplit(fW, sm, tid);
    int R0 = blockIdx.x * 128;
#pragma unroll 2
    for (int e = 0; e < 8; e++) {
        int idx = e * 256 + tid;
        int r = idx >> 4, c4 = idx & 15;
        int R = R0 + r;
        int bb = R >> 12, qh = (R >> 6) & 63, qw = R & 63;
        int ih = qh >> 1, iw = qw >> 1;
        int sh = ((qh + 63) & 63) >> 1, sw_ = ((qw + 63) & 63) >> 1;
        float4 a = ((const float4*)g_tok)[((bb * 32 + ih) * 32 + iw) * 16 + c4];
        float4 s = ((const float4*)g_tok)[524288 + ((bb * 32 + sh) * 32 + sw_) * 16 + c4];
        store_x4(sm, r, c4, make_float4(a.x + s.x, a.y + s.y, a.z + s.z, a.w + s.w));
    }
    __syncthreads();
    float v[2][16];
    // ---- layer 1: fuse ----
    gemm_ln_gelu(sm, sm + CPO, tid, v);
    __syncthreads();                      // all reads of X/W done
    writeback_split(sm, tid, v);
    load_wsplit(oW, sm, tid);
    __syncthreads();
    // ---- layer 2: out ----
    gemm_ln_gelu(sm, sm + CPO + 192, tid, v);
    // write unique rows straight from registers (coalesced float2 within quads)
    int w = tid >> 5, lane = tid & 31, g = lane >> 2, q = lane & 3;
    int R = R0 + 16 * w + g;
#pragma unroll
    for (int j = 0; j < 8; j++) {
        *(float2*)&g_S[R * 64 + 8 * j + 2 * q]       = make_float2(v[0][2*j], v[0][2*j+1]);
        *(float2*)&g_S[(R + 8) * 64 + 8 * j + 2 * q] = make_float2(v[1][2*j], v[1][2*j+1]);
    }
}

// ---------------------------------------------------------------------------
// K3b: pure broadcast stream — each thread: 1 float4 read (L2-hot), 9 writes.
// 131072 rows x 16 float4 = 2,097,152 threads.
// ---------------------------------------------------------------------------
__global__ void __launch_bounds__(256) k3b_bcast(float* __restrict__ out) {
    int tid = blockIdx.x * blockDim.x + threadIdx.x;
    int c4 = tid & 15, R = tid >> 4;
    float4 val = __ldg((const float4*)g_S + tid);
    int bb = R >> 12, qh = (R >> 6) & 63, qw = R & 63;
    float4* o4 = (float4*)out;
    int base = (bb * 36864 + qh * 3 * HHH + qw * 3) * 16 + c4;
#pragma unroll
    for (int dh = 0; dh < 3; dh++)
#pragma unroll
        for (int dw = 0; dw < 3; dw++)
            o4[base + (dh * HHH + dw) * 16] = val;
}

// ---------------------------------------------------------------------------
extern "C" void kernel_launch(void* const* d_in, const int* in_sizes, int n_in,
                              void* d_out, int out_size) {
    const float* h_pixel = (const float*)d_in[0];
    const float* tW  = (const float*)d_in[1];
    const float* tb  = (const float*)d_in[2];
    const float* tg  = (const float*)d_in[3];
    const float* tbe = (const float*)d_in[4];
    const float* fW  = (const float*)d_in[5];
    const float* fb  = (const float*)d_in[6];
    const float* fg  = (const float*)d_in[7];
    const float* fbe = (const float*)d_in[8];
    const float* oW  = (const float*)d_in[9];
    const float* ob  = (const float*)d_in[10];
    const float* og  = (const float*)d_in[11];
    const float* obe = (const float*)d_in[12];
    float* out = (float*)d_out;

    cudaFuncSetAttribute(k2_token,    cudaFuncAttributeMaxDynamicSharedMemorySize, SMB);
    cudaFuncSetAttribute(k3a_compute, cudaFuncAttributeMaxDynamicSharedMemorySize, SMB);

    k1_subsum<<<8192, 256>>>(h_pixel);
    k2_token<<<512, 256, SMB>>>(tW, tb, tg, tbe);
    k3a_compute<<<1024, 256, SMB>>>(fW, fb, fg, fbe, oW, ob, og, obe);
    k3b_bcast<<<8192, 256>>>(out);
}

// round 16
// speedup vs baseline: 1.1718x; 1.1718x over previous
#include <cuda_runtime.h>
#include <cuda_bf16.h>
#include <math.h>
#include <stdint.h>

#define EPS  1e-5f
#define HHH  192
// smem layout (u32/float offsets)
#define CPO  0                 // params: up to 6 x 64 floats (384)
#define XHO  384               // X hi: 128 rows x 36 u32 (bf16x2 per k-pair)
#define XLO  4992              // X lo: 128 x 36
#define WHO  9600              // W hi: 16 pair-rows x 68 float2 (2176 u32)
#define WLO  11776             // W lo: same
#define SMF  13952
#define SMB  (SMF * 4)         // 55808 bytes

// Scratch (device globals — allocation-free)
__device__ __align__(16) float g_S[32 * 64 * 64 * 64];        // 3x3 sub-block sums
__device__ __align__(16) float g_tok[2 * 32 * 32 * 32 * 64];  // tokens [p][b][i][j][c]

__device__ __forceinline__ unsigned short f2b(float x) {
    return __bfloat16_as_ushort(__float2bfloat16_rn(x));
}
__device__ __forceinline__ float b2f(unsigned short u) {
    return __uint_as_float(((uint32_t)u) << 16);
}
__device__ __forceinline__ void mma16(float* d, const uint32_t* a, uint32_t b0, uint32_t b1) {
    asm volatile(
        "mma.sync.aligned.m16n8k16.row.col.f32.bf16.bf16.f32 "
        "{%0,%1,%2,%3}, {%4,%5,%6,%7}, {%8,%9}, {%0,%1,%2,%3};"
        : "+f"(d[0]), "+f"(d[1]), "+f"(d[2]), "+f"(d[3])
        : "r"(a[0]), "r"(a[1]), "r"(a[2]), "r"(a[3]), "r"(b0), "r"(b1));
}
__device__ __forceinline__ float gelu_exact(float v) {
    return 0.5f * v * (1.0f + erff(v * 0.7071067811865476f));
}

// ---------------------------------------------------------------------------
// K1: 3x3 sub-block sums for 16 batches starting at b0. grid 4096.
// ---------------------------------------------------------------------------
__global__ void __launch_bounds__(256) k1_subsum(const float* __restrict__ x, int b0) {
    int tid = blockIdx.x * blockDim.x + threadIdx.x;   // [0, 1048576)
    int c4 = tid & 15;
    int sw = (tid >> 4) & 63;
    int sh = (tid >> 10) & 63;
    int b  = b0 + (tid >> 16);
    const float4* x4 = (const float4*)x;
    float4 acc = make_float4(0.f, 0.f, 0.f, 0.f);
    int rowbase = (b * HHH + sh * 3) * HHH + sw * 3;
#pragma unroll
    for (int dh = 0; dh < 3; dh++)
#pragma unroll
        for (int dw = 0; dw < 3; dw++) {
            float4 v = x4[(rowbase + dh * HHH + dw) * 16 + c4];
            acc.x += v.x; acc.y += v.y; acc.z += v.z; acc.w += v.w;
        }
    ((float4*)g_S)[tid + (b0 << 16)] = acc;
}

// split 4 consecutive k (k=4c4..4c4+3) of row r into packed bf16x2 hi/lo tiles
__device__ __forceinline__ void store_x4(float* sm, int r, int c4, float4 xv) {
    unsigned short h0 = f2b(xv.x), h1 = f2b(xv.y), h2 = f2b(xv.z), h3 = f2b(xv.w);
    uint32_t hh0 = (uint32_t)h0 | ((uint32_t)h1 << 16);
    uint32_t hh1 = (uint32_t)h2 | ((uint32_t)h3 << 16);
    unsigned short l0 = f2b(xv.x - b2f(h0)), l1 = f2b(xv.y - b2f(h1));
    unsigned short l2 = f2b(xv.z - b2f(h2)), l3 = f2b(xv.w - b2f(h3));
    uint32_t ll0 = (uint32_t)l0 | ((uint32_t)l1 << 16);
    uint32_t ll1 = (uint32_t)l2 | ((uint32_t)l3 << 16);
    ((uint2*)(sm + XHO))[r * 18 + c4] = make_uint2(hh0, hh1);
    ((uint2*)(sm + XLO))[r * 18 + c4] = make_uint2(ll0, ll1);
}

// W[k][n] (64x64) -> paired bf16x2 hi/lo tiles.
__device__ __forceinline__ void load_wsplit(const float* __restrict__ W, float* sm, int tid) {
    unsigned short* wh16 = (unsigned short*)(sm + WHO);
    unsigned short* wl16 = (unsigned short*)(sm + WLO);
#pragma unroll
    for (int e = 0; e < 4; e++) {
        int idx = e * 256 + tid;
        int k = idx >> 4, n4 = idx & 15;
        float4 wv = ((const float4*)W)[idx];
        int ks = k >> 4, kk = k & 15, pkl = kk >> 1;
        int row = ks * 4 + (pkl & 3), half = pkl >> 2, par = kk & 1;
        float vv[4] = { wv.x, wv.y, wv.z, wv.w };
#pragma unroll
        for (int jj = 0; jj < 4; jj++) {
            int n = 4 * n4 + jj;
            int u16i = ((((row * 68 + n) * 2 + half) << 1) | par);
            unsigned short hb = f2b(vv[jj]);
            wh16[u16i] = hb;
            wl16[u16i] = f2b(vv[jj] - b2f(hb));
        }
    }
}

// GEMM(128x64 @ 64x64) via mma.sync bf16 m16n8k16, 3-pass split + LN + GELU.
__device__ __forceinline__ void gemm_ln_gelu(const float* sm, const float* cp, int tid,
                                             float v[2][16]) {
    int w = tid >> 5, lane = tid & 31, g = lane >> 2, q = lane & 3;
    const uint32_t* xh = (const uint32_t*)(sm + XHO);
    const uint32_t* xl = (const uint32_t*)(sm + XLO);
    const uint2* wh2 = (const uint2*)(sm + WHO);
    const uint2* wl2 = (const uint2*)(sm + WLO);
    float acc[8][4];
#pragma unroll
    for (int j = 0; j < 8; j++) {
        float2 b2 = *(const float2*)(cp + 8 * j + 2 * q);
        acc[j][0] = b2.x; acc[j][1] = b2.y; acc[j][2] = b2.x; acc[j][3] = b2.y;
    }
    int r0 = 16 * w;
    const uint32_t* xh0 = xh + (r0 + g) * 36;
    const uint32_t* xh1 = xh + (r0 + 8 + g) * 36;
    const uint32_t* xl0 = xl + (r0 + g) * 36;
    const uint32_t* xl1 = xl + (r0 + 8 + g) * 36;
#pragma unroll
    for (int ks = 0; ks < 4; ks++) {
        int pk = 8 * ks + q;
        uint32_t Ahi[4] = { xh0[pk], xh1[pk], xh0[pk + 4], xh1[pk + 4] };
        uint32_t Alo[4] = { xl0[pk], xl1[pk], xl0[pk + 4], xl1[pk + 4] };
        const uint2* whr = wh2 + (ks * 4 + q) * 68 + g;
        const uint2* wlr = wl2 + (ks * 4 + q) * 68 + g;
#pragma unroll
        for (int jh = 0; jh < 2; jh++) {
            uint2 wh[4], wl[4];
#pragma unroll
            for (int j4 = 0; j4 < 4; j4++) {
                wh[j4] = whr[8 * (4 * jh + j4)];
                wl[j4] = wlr[8 * (4 * jh + j4)];
            }
#pragma unroll
            for (int j4 = 0; j4 < 4; j4++) mma16(acc[4*jh+j4], Ahi, wh[j4].x, wh[j4].y);
#pragma unroll
            for (int j4 = 0; j4 < 4; j4++) mma16(acc[4*jh+j4], Ahi, wl[j4].x, wl[j4].y);
#pragma unroll
            for (int j4 = 0; j4 < 4; j4++) mma16(acc[4*jh+j4], Alo, wh[j4].x, wh[j4].y);
        }
    }
#pragma unroll
    for (int j = 0; j < 8; j++) {
        v[0][2 * j] = acc[j][0]; v[0][2 * j + 1] = acc[j][1];
        v[1][2 * j] = acc[j][2]; v[1][2 * j + 1] = acc[j][3];
    }
#pragma unroll
    for (int t = 0; t < 2; t++) {
        float s = 0.f;
#pragma unroll
        for (int i = 0; i < 16; i++) s += v[t][i];
        s += __shfl_xor_sync(0xffffffffu, s, 1);
        s += __shfl_xor_sync(0xffffffffu, s, 2);
        float mean = s * (1.0f / 64.0f);
        float var = 0.f;
#pragma unroll
        for (int i = 0; i < 16; i++) { float d = v[t][i] - mean; var += d * d; }
        var += __shfl_xor_sync(0xffffffffu, var, 1);
        var += __shfl_xor_sync(0xffffffffu, var, 2);
        float rstd = rsqrtf(var * (1.0f / 64.0f) + EPS);
#pragma unroll
        for (int j = 0; j < 8; j++) {
            float2 gm = *(const float2*)(cp + 64  + 8 * j + 2 * q);
            float2 bt = *(const float2*)(cp + 128 + 8 * j + 2 * q);
            v[t][2 * j]     = gelu_exact((v[t][2 * j]     - mean) * rstd * gm.x + bt.x);
            v[t][2 * j + 1] = gelu_exact((v[t][2 * j + 1] - mean) * rstd * gm.y + bt.y);
        }
    }
}

// write layer activations back as split bf16x2 (cols 8j+2q form a k-pair)
__device__ __forceinline__ void writeback_split(float* sm, int tid, const float v[2][16]) {
    uint32_t* xh = (uint32_t*)(sm + XHO);
    uint32_t* xl = (uint32_t*)(sm + XLO);
    int w = tid >> 5, lane = tid & 31, g = lane >> 2, q = lane & 3;
#pragma unroll
    for (int t = 0; t < 2; t++) {
        int r = 16 * w + g + 8 * t;
#pragma unroll
        for (int j = 0; j < 8; j++) {
            int pk = 4 * j + q;
            float a = v[t][2 * j], b = v[t][2 * j + 1];
            unsigned short ha = f2b(a), hb = f2b(b);
            xh[r * 36 + pk] = (uint32_t)ha | ((uint32_t)hb << 16);
            unsigned short la = f2b(a - b2f(ha)), lb = f2b(b - b2f(hb));
            xl[r * 36 + pk] = (uint32_t)la | ((uint32_t)lb << 16);
        }
    }
}

// ---------------------------------------------------------------------------
// K2: token projection (both paths) for 16 batches at b0. 256 CTAs.
// local R in [0,32768): p = R>>14, bbl = (R>>10)&15, ii, jj.
// ---------------------------------------------------------------------------
__global__ void __launch_bounds__(256, 3) k2_token(
    const float* __restrict__ tW, const float* __restrict__ tb,
    const float* __restrict__ tg, const float* __restrict__ tbe, int b0)
{
    extern __shared__ __align__(16) float sm[];
    int tid = threadIdx.x;
    if (tid < 64) {
        sm[CPO + tid] = tb[tid]; sm[CPO + 64 + tid] = tg[tid]; sm[CPO + 128 + tid] = tbe[tid];
    }
    load_wsplit(tW, sm, tid);
    int R0 = blockIdx.x * 128;
#pragma unroll 2
    for (int e = 0; e < 8; e++) {
        int idx = e * 256 + tid;
        int r = idx >> 4, c4 = idx & 15;
        int R = R0 + r;
        int p = R >> 14, rem = R & 16383;
        int bb = b0 + (rem >> 10), ii = (rem >> 5) & 31, jj = rem & 31;
        int r0, r1, q0, q1;
        if (p == 0) { r0 = 2 * ii;            r1 = 2 * ii + 1;
                      q0 = 2 * jj;            q1 = 2 * jj + 1; }
        else        { r0 = (2 * ii + 1) & 63; r1 = (2 * ii + 2) & 63;
                      q0 = (2 * jj + 1) & 63; q1 = (2 * jj + 2) & 63; }
        const float4* Sb = (const float4*)g_S + bb * 65536;
        float4 s0 = Sb[(r0 * 64 + q0) * 16 + c4];
        float4 s1 = Sb[(r0 * 64 + q1) * 16 + c4];
        float4 s2 = Sb[(r1 * 64 + q0) * 16 + c4];
        float4 s3 = Sb[(r1 * 64 + q1) * 16 + c4];
        store_x4(sm, r, c4,
            make_float4((s0.x + s1.x + s2.x + s3.x) * (1.0f / 36.0f),
                        (s0.y + s1.y + s2.y + s3.y) * (1.0f / 36.0f),
                        (s0.z + s1.z + s2.z + s3.z) * (1.0f / 36.0f),
                        (s0.w + s1.w + s2.w + s3.w) * (1.0f / 36.0f)));
    }
    __syncthreads();
    float v[2][16];
    gemm_ln_gelu(sm, sm + CPO, tid, v);
    int w = tid >> 5, lane = tid & 31, g = lane >> 2, q = lane & 3;
    int R = R0 + 16 * w + g;
    int p = R >> 14;                       // 128-row tiles never cross p boundary
    int Rg = R + p * 16384 + b0 * 1024;    // global token row
#pragma unroll
    for (int j = 0; j < 8; j++) {
        *(float2*)&g_tok[Rg * 64 + 8 * j + 2 * q]       = make_float2(v[0][2*j], v[0][2*j+1]);
        *(float2*)&g_tok[(Rg + 8) * 64 + 8 * j + 2 * q] = make_float2(v[1][2*j], v[1][2*j+1]);
    }
}

// ---------------------------------------------------------------------------
// K3: fuse + out layers per unique 3x3 block for 16 batches at b0 (512 CTAs),
// fused broadcast of each row to its 9 output pixels.
// ---------------------------------------------------------------------------
__global__ void __launch_bounds__(256, 3) k3_fuse_out(
    const float* __restrict__ fW, const float* __restrict__ fb,
    const float* __restrict__ fg, const float* __restrict__ fbe,
    const float* __restrict__ oW, const float* __restrict__ ob,
    const float* __restrict__ og, const float* __restrict__ obe,
    float* __restrict__ out, int b0)
{
    extern __shared__ __align__(16) float sm[];
    int tid = threadIdx.x;
    if (tid < 64) {
        sm[CPO + tid]       = fb[tid]; sm[CPO + 64 + tid]  = fg[tid]; sm[CPO + 128 + tid] = fbe[tid];
        sm[CPO + 192 + tid] = ob[tid]; sm[CPO + 256 + tid] = og[tid]; sm[CPO + 320 + tid] = obe[tid];
    }
    load_wsplit(fW, sm, tid);
    int R0 = blockIdx.x * 128;
#pragma unroll 2
    for (int e = 0; e < 8; e++) {
        int idx = e * 256 + tid;
        int r = idx >> 4, c4 = idx & 15;
        int R = R0 + r;
        int bb = b0 + (R >> 12), qh = (R >> 6) & 63, qw = R & 63;
        int ih = qh >> 1, iw = qw >> 1;
        int sh = ((qh + 63) & 63) >> 1, sw_ = ((qw + 63) & 63) >> 1;
        float4 a = ((const float4*)g_tok)[((bb * 32 + ih) * 32 + iw) * 16 + c4];
        float4 s = ((const float4*)g_tok)[524288 + ((bb * 32 + sh) * 32 + sw_) * 16 + c4];
        store_x4(sm, r, c4, make_float4(a.x + s.x, a.y + s.y, a.z + s.z, a.w + s.w));
    }
    __syncthreads();
    float v[2][16];
    // ---- layer 1: fuse ----
    gemm_ln_gelu(sm, sm + CPO, tid, v);
    __syncthreads();                      // all reads of X/W done
    writeback_split(sm, tid, v);
    load_wsplit(oW, sm, tid);
    __syncthreads();
    // ---- layer 2: out ----
    gemm_ln_gelu(sm, sm + CPO + 192, tid, v);
    __syncthreads();                      // X/W reads done; reuse X region as ys
    float* ys = sm + XHO;                 // 128 rows x stride 68 floats
    {
        int w = tid >> 5, lane = tid & 31, g = lane >> 2, q = lane & 3;
        int r0 = 16 * w + g;
#pragma unroll
        for (int j = 0; j < 8; j++) {
            *(float2*)&ys[r0 * 68 + 8 * j + 2 * q]       = make_float2(v[0][2*j], v[0][2*j+1]);
            *(float2*)&ys[(r0 + 8) * 68 + 8 * j + 2 * q] = make_float2(v[1][2*j], v[1][2*j+1]);
        }
    }
    __syncthreads();
    // coalesced 3x3 broadcast
    float4* o4 = (float4*)out;
#pragma unroll 2
    for (int e = 0; e < 8; e++) {
        int idx = e * 256 + tid;
        int r = idx >> 4, c4 = idx & 15;
        float4 val = *(float4*)(ys + r * 68 + 4 * c4);
        int R = R0 + r;
        int bb = b0 + (R >> 12), qh = (R >> 6) & 63, qw = R & 63;
        int base = (bb * 36864 + qh * 3 * HHH + qw * 3) * 16 + c4;
#pragma unroll
        for (int dh = 0; dh < 3; dh++)
#pragma unroll
            for (int dw = 0; dw < 3; dw++)
                o4[base + (dh * HHH + dw) * 16] = val;
    }
}

// ---------------------------------------------------------------------------
extern "C" void kernel_launch(void* const* d_in, const int* in_sizes, int n_in,
                              void* d_out, int out_size) {
    const float* h_pixel = (const float*)d_in[0];
    const float* tW  = (const float*)d_in[1];
    const float* tb  = (const float*)d_in[2];
    const float* tg  = (const float*)d_in[3];
    const float* tbe = (const float*)d_in[4];
    const float* fW  = (const float*)d_in[5];
    const float* fb  = (const float*)d_in[6];
    const float* fg  = (const float*)d_in[7];
    const float* fbe = (const float*)d_in[8];
    const float* oW  = (const float*)d_in[9];
    const float* ob  = (const float*)d_in[10];
    const float* og  = (const float*)d_in[11];
    const float* obe = (const float*)d_in[12];
    float* out = (float*)d_out;

    // one-time infra (created during the uncaptured correctness run)
    static cudaStream_t s2 = []() { cudaStream_t s; cudaStreamCreate(&s); return s; }();
    static cudaEvent_t eFork = []() { cudaEvent_t e; cudaEventCreateWithFlags(&e, cudaEventDisableTiming); return e; }();
    static cudaEvent_t eJoin = []() { cudaEvent_t e; cudaEventCreateWithFlags(&e, cudaEventDisableTiming); return e; }();
    static bool attrs_set = []() {
        cudaFuncSetAttribute(k2_token,    cudaFuncAttributeMaxDynamicSharedMemorySize, SMB);
        cudaFuncSetAttribute(k3_fuse_out, cudaFuncAttributeMaxDynamicSharedMemorySize, SMB);
        return true;
    }();
    (void)attrs_set;

    // fork: chain A (b 0-15) on default stream, chain B (b 16-31) on s2
    cudaEventRecord(eFork, 0);
    cudaStreamWaitEvent(s2, eFork, 0);

    k1_subsum<<<4096, 256, 0, 0>>>(h_pixel, 0);
    k1_subsum<<<4096, 256, 0, s2>>>(h_pixel, 16);

    k2_token<<<256, 256, SMB, 0>>>(tW, tb, tg, tbe, 0);
    k2_token<<<256, 256, SMB, s2>>>(tW, tb, tg, tbe, 16);

    k3_fuse_out<<<512, 256, SMB, 0>>>(fW, fb, fg, fbe, oW, ob, og, obe, out, 0);
    k3_fuse_out<<<512, 256, SMB, s2>>>(fW, fb, fg, fbe, oW, ob, og, obe, out, 16);

    // join
    cudaEventRecord(eJoin, s2);
    cudaStreamWaitEvent(0, eJoin, 0);
}